// round 16
// baseline (speedup 1.0000x reference)
#include <cuda_runtime.h>
#include <cuda_bf16.h>
#include <mma.h>
#include <stdint.h>

using namespace nvcuda;

// Problem constants
#define B      2
#define S      2048
#define DM     1024
#define H      16
#define DH     64
#define BH     (B*H)          // 32
#define MTOT   (B*S)          // 4096
#define NQKV   (3*DM)         // 3072
#define IGNORE_VAL (-1e5f)

// ---------------------------------------------------------------------------
// Global scratch. Referenced ONLY from device code (R11 lesson).
// ---------------------------------------------------------------------------
__device__ __align__(16) __nv_bfloat16 g_Qh[BH*S*DH];
__device__ __align__(16) __nv_bfloat16 g_Ql[BH*S*DH];
__device__ __align__(16) __nv_bfloat16 g_Kh[BH*S*DH];
__device__ __align__(16) __nv_bfloat16 g_Kl[BH*S*DH];
__device__ __align__(16) __nv_bfloat16 g_Vh[BH*S*DH];
__device__ __align__(16) __nv_bfloat16 g_Vl[BH*S*DH];

__device__ __align__(16) __nv_bfloat16 g_xh[MTOT*DM];
__device__ __align__(16) __nv_bfloat16 g_xl[MTOT*DM];
__device__ __align__(16) __nv_bfloat16 g_wqh[NQKV*DM];
__device__ __align__(16) __nv_bfloat16 g_wql[NQKV*DM];
__device__ __align__(16) __nv_bfloat16 g_woh[DM*DM];
__device__ __align__(16) __nv_bfloat16 g_wol[DM*DM];
__device__ __align__(16) __nv_bfloat16 g_zh[MTOT*DM];
__device__ __align__(16) __nv_bfloat16 g_zl[MTOT*DM];

// ---------------------------------------------------------------------------
// cp.async helpers
// ---------------------------------------------------------------------------
__device__ __forceinline__ uint32_t smem_u32(const void* p) {
    uint32_t a;
    asm("{ .reg .u64 t; cvta.to.shared.u64 t, %1; cvt.u32.u64 %0, t; }" : "=r"(a) : "l"(p));
    return a;
}
__device__ __forceinline__ void cp_async16(uint32_t sa, const void* g) {
    asm volatile("cp.async.cg.shared.global [%0], [%1], 16;" :: "r"(sa), "l"(g));
}
__device__ __forceinline__ void cp_commit() {
    asm volatile("cp.async.commit_group;");
}
template<int N>
__device__ __forceinline__ void cp_wait() {
    asm volatile("cp.async.wait_group %0;" :: "n"(N));
}

// ---------------------------------------------------------------------------
// Pre-passes
// ---------------------------------------------------------------------------
__global__ void split_x_kernel(const float* __restrict__ x) {
    int i = blockIdx.x * 256 + threadIdx.x;
    if (i < MTOT * DM) {
        float v = x[i];
        __nv_bfloat16 hi = __float2bfloat16(v);
        __nv_bfloat16 lo = __float2bfloat16(v - __bfloat162float(hi));
        g_xh[i] = hi; g_xl[i] = lo;
    }
}

__global__ void pack_wqkv_kernel(const float* __restrict__ Wq,
                                 const float* __restrict__ Wk,
                                 const float* __restrict__ Wv) {
    int i = blockIdx.x * 256 + threadIdx.x;
    if (i < NQKV * DM) {
        int n = i >> 10, k = i & 1023;
        int mat = n >> 10, h = (n >> 6) & 15, e = n & 63;
        const float* W = (mat == 0) ? Wq : (mat == 1 ? Wk : Wv);
        float v = W[(h * DM + k) * DH + e];
        __nv_bfloat16 hi = __float2bfloat16(v);
        __nv_bfloat16 lo = __float2bfloat16(v - __bfloat162float(hi));
        g_wqh[i] = hi; g_wql[i] = lo;
    }
}

__global__ void pack_wo_kernel(const float* __restrict__ Wo) {
    int i = blockIdx.x * 256 + threadIdx.x;
    if (i < DM * DM) {
        int n = i >> 10, k = i & 1023;
        float v = Wo[k * DM + n];
        __nv_bfloat16 hi = __float2bfloat16(v);
        __nv_bfloat16 lo = __float2bfloat16(v - __bfloat162float(hi));
        g_woh[i] = hi; g_wol[i] = lo;
    }
}

// ---------------------------------------------------------------------------
// WMMA GEMM, 2-stage cp.async pipeline, K-chunk 64.
// Block 128x128, 512 threads, 16 warps (4Mx4N), warp tile 32x32 (2x2 frags).
// __launch_bounds__(512,1) caps regs at 128 -> 16 warps/SM (4 per SMSP).
// Dynamic smem: 2 stages x 4 tiles x (128 x 72 bf16) = 147456 B.
// ---------------------------------------------------------------------------
#define LDS2    72
#define TILE2   (128*LDS2)
#define STAGE2  (4*TILE2)
#define GSMEM_B (2*STAGE2*2)      // 147456 bytes

template<int MODE>
__device__ __forceinline__ void gemm_prefetch(__nv_bfloat16* sm, int stg, int ch,
                                              int m0, int n0, int tid) {
    const __nv_bfloat16* Ah = (MODE == 0) ? g_xh : g_zh;
    const __nv_bfloat16* Al = (MODE == 0) ? g_xl : g_zl;
    const __nv_bfloat16* Bh = (MODE == 0) ? g_wqh : g_woh;
    const __nv_bfloat16* Bl = (MODE == 0) ? g_wql : g_wol;
    __nv_bfloat16* base = sm + stg * STAGE2;
    #pragma unroll
    for (int i = 0; i < 2; i++) {
        int idx = tid + i * 512;           // 0..1023
        int row = idx >> 3, sl = idx & 7;
        uint32_t soff = (uint32_t)(row * LDS2 + sl * 8);
        size_t ga = (size_t)(m0 + row) * DM + ch * 64 + sl * 8;
        size_t gb = (size_t)(n0 + row) * DM + ch * 64 + sl * 8;
        cp_async16(smem_u32(base + 0 * TILE2 + soff), Ah + ga);
        cp_async16(smem_u32(base + 1 * TILE2 + soff), Al + ga);
        cp_async16(smem_u32(base + 2 * TILE2 + soff), Bh + gb);
        cp_async16(smem_u32(base + 3 * TILE2 + soff), Bl + gb);
    }
}

template<int MODE>
__global__ void __launch_bounds__(512, 1) gemm_wmma(
    const float* __restrict__ bq, const float* __restrict__ bk,
    const float* __restrict__ bv, const float* __restrict__ bo,
    float* __restrict__ out)
{
    extern __shared__ __align__(16) __nv_bfloat16 sm[];

    const int tid = threadIdx.x;
    const int wid = tid >> 5;
    const int ln  = tid & 31;
    const int warpM = wid >> 2;          // 0..3
    const int warpN = wid & 3;           // 0..3
    const int m0 = blockIdx.x * 128;
    const int n0 = blockIdx.y * 128;

    wmma::fragment<wmma::accumulator, 16, 16, 16, float> c[2][2];
    #pragma unroll
    for (int mt = 0; mt < 2; mt++)
        #pragma unroll
        for (int nt = 0; nt < 2; nt++)
            wmma::fill_fragment(c[mt][nt], 0.0f);

    gemm_prefetch<MODE>(sm, 0, 0, m0, n0, tid);
    cp_commit();

    for (int ch = 0; ch < 16; ch++) {
        if (ch + 1 < 16) {
            gemm_prefetch<MODE>(sm, (ch + 1) & 1, ch + 1, m0, n0, tid);
            cp_commit();
            cp_wait<1>();
        } else {
            cp_wait<0>();
        }
        __syncthreads();

        __nv_bfloat16* st = sm + (ch & 1) * STAGE2;
        __nv_bfloat16* sAh = st;
        __nv_bfloat16* sAl = st + TILE2;
        __nv_bfloat16* sBh = st + 2 * TILE2;
        __nv_bfloat16* sBl = st + 3 * TILE2;

        #pragma unroll
        for (int kk = 0; kk < 4; kk++) {
            wmma::fragment<wmma::matrix_a, 16, 16, 16, __nv_bfloat16, wmma::row_major> aH[2], aL[2];
            #pragma unroll
            for (int mt = 0; mt < 2; mt++) {
                int off = (warpM * 32 + mt * 16) * LDS2 + kk * 16;
                wmma::load_matrix_sync(aH[mt], sAh + off, LDS2);
                wmma::load_matrix_sync(aL[mt], sAl + off, LDS2);
            }
            #pragma unroll
            for (int nt = 0; nt < 2; nt++) {
                wmma::fragment<wmma::matrix_b, 16, 16, 16, __nv_bfloat16, wmma::col_major> bH, bL;
                int off = (warpN * 32 + nt * 16) * LDS2 + kk * 16;
                wmma::load_matrix_sync(bH, sBh + off, LDS2);
                wmma::load_matrix_sync(bL, sBl + off, LDS2);
                #pragma unroll
                for (int mt = 0; mt < 2; mt++) {
                    wmma::mma_sync(c[mt][nt], aH[mt], bH, c[mt][nt]);
                    wmma::mma_sync(c[mt][nt], aH[mt], bL, c[mt][nt]);
                    wmma::mma_sync(c[mt][nt], aL[mt], bH, c[mt][nt]);
                }
            }
        }
        __syncthreads();
    }

    // ---- epilogue: stage each 16x16 C tile through per-warp smem ----
    float* stage = reinterpret_cast<float*>(sm) + wid * 256;   // 16KB total
    #pragma unroll
    for (int mt = 0; mt < 2; mt++) {
        #pragma unroll
        for (int nt = 0; nt < 2; nt++) {
            wmma::store_matrix_sync(stage, c[mt][nt], 16, wmma::mem_row_major);
            __syncwarp();
            int mb = m0 + warpM * 32 + mt * 16;
            int nb = n0 + warpN * 32 + nt * 16;
            #pragma unroll
            for (int j = 0; j < 8; j++) {
                int idx = ln * 8 + j;
                int r = idx >> 4, cc = idx & 15;
                int m = mb + r, n = nb + cc;
                float v = stage[idx];
                if (MODE == 0) {
                    int bb = m >> 11, s = m & 2047;
                    int mat = n >> 10, h = (n >> 6) & 15, e = n & 63;
                    const float* bias = (mat == 0) ? bq : (mat == 1 ? bk : bv);
                    v += bias[h * DH + e];
                    __nv_bfloat16 hi = __float2bfloat16(v);
                    __nv_bfloat16 lo = __float2bfloat16(v - __bfloat162float(hi));
                    size_t off = ((size_t)(bb * H + h) * S + s) * DH + e;
                    __nv_bfloat16* dh = (mat == 0) ? g_Qh : (mat == 1 ? g_Kh : g_Vh);
                    __nv_bfloat16* dl = (mat == 0) ? g_Ql : (mat == 1 ? g_Kl : g_Vl);
                    dh[off] = hi; dl[off] = lo;
                } else {
                    out[(size_t)m * DM + n] = v + bo[n];
                }
            }
            __syncwarp();
        }
    }
}

// ---------------------------------------------------------------------------
// Causal flash attention: wmma QK^T and P.V, SIMT online softmax (proven).
// ---------------------------------------------------------------------------
#define LDA      72
#define ATT_SMEM 73728

__global__ void __launch_bounds__(256) attn_wmma() {
    extern __shared__ __align__(16) char smem_raw[];
    __nv_bfloat16* sQh = (__nv_bfloat16*)(smem_raw);
    __nv_bfloat16* sQl = (__nv_bfloat16*)(smem_raw + 9216);
    __nv_bfloat16* sKh = (__nv_bfloat16*)(smem_raw + 18432);
    __nv_bfloat16* sKl = (__nv_bfloat16*)(smem_raw + 27648);
    __nv_bfloat16* sVh = (__nv_bfloat16*)(smem_raw + 36864);
    __nv_bfloat16* sVl = (__nv_bfloat16*)(smem_raw + 46080);
    float*         sS  = (float*)(smem_raw + 55296);

    const int tid = threadIdx.x;
    const int wid = tid >> 5;
    const int tx  = tid & 15;
    const int ty  = tid >> 4;
    const int bh  = blockIdx.y;
    const int qt  = (int)gridDim.x - 1 - (int)blockIdx.x;

    const int mt  = wid >> 1;
    const int n0t = (wid & 1) * 2;

    const __nv_bfloat16* Qhp = g_Qh + ((size_t)bh * S + qt * 64) * DH;
    const __nv_bfloat16* Qlp = g_Ql + ((size_t)bh * S + qt * 64) * DH;

    #pragma unroll
    for (int i = 0; i < 2; i++) {
        int idx = tid + i * 256;
        int row = idx >> 3, sl = idx & 7;
        int se = row * LDA + sl * 8;
        *(uint4*)(sQh + se) = *(const uint4*)(Qhp + row * 64 + sl * 8);
        *(uint4*)(sQl + se) = *(const uint4*)(Qlp + row * 64 + sl * 8);
    }

    float m_i[4], l_i[4], acc[4][4] = {};
    #pragma unroll
    for (int i = 0; i < 4; i++) { m_i[i] = -1e30f; l_i[i] = 0.f; }

    for (int kt = 0; kt <= qt; kt++) {
        const __nv_bfloat16* Khp = g_Kh + ((size_t)bh * S + kt * 64) * DH;
        const __nv_bfloat16* Klp = g_Kl + ((size_t)bh * S + kt * 64) * DH;
        const __nv_bfloat16* Vhp = g_Vh + ((size_t)bh * S + kt * 64) * DH;
        const __nv_bfloat16* Vlp = g_Vl + ((size_t)bh * S + kt * 64) * DH;
        #pragma unroll
        for (int i = 0; i < 2; i++) {
            int idx = tid + i * 256;
            int row = idx >> 3, sl = idx & 7;
            int se = row * LDA + sl * 8;
            int ge = row * 64 + sl * 8;
            *(uint4*)(sKh + se) = *(const uint4*)(Khp + ge);
            *(uint4*)(sKl + se) = *(const uint4*)(Klp + ge);
            *(uint4*)(sVh + se) = *(const uint4*)(Vhp + ge);
            *(uint4*)(sVl + se) = *(const uint4*)(Vlp + ge);
        }
        __syncthreads();

        {
            wmma::fragment<wmma::accumulator, 16, 16, 16, float> sacc[2];
            wmma::fill_fragment(sacc[0], 0.0f);
            wmma::fill_fragment(sacc[1], 0.0f);
            #pragma unroll
            for (int ks = 0; ks < 4; ks++) {
                wmma::fragment<wmma::matrix_a, 16, 16, 16, __nv_bfloat16, wmma::row_major> aH, aL;
                wmma::load_matrix_sync(aH, sQh + (mt * 16) * LDA + ks * 16, LDA);
                wmma::load_matrix_sync(aL, sQl + (mt * 16) * LDA + ks * 16, LDA);
                #pragma unroll
                for (int j = 0; j < 2; j++) {
                    wmma::fragment<wmma::matrix_b, 16, 16, 16, __nv_bfloat16, wmma::col_major> bH, bL;
                    wmma::load_matrix_sync(bH, sKh + ((n0t + j) * 16) * LDA + ks * 16, LDA);
                    wmma::load_matrix_sync(bL, sKl + ((n0t + j) * 16) * LDA + ks * 16, LDA);
                    wmma::mma_sync(sacc[j], aH, bH, sacc[j]);
                    wmma::mma_sync(sacc[j], aH, bL, sacc[j]);
                    wmma::mma_sync(sacc[j], aL, bH, sacc[j]);
                }
            }
            wmma::store_matrix_sync(sS + (mt * 16) * LDA + n0t * 16, sacc[0], LDA, wmma::mem_row_major);
            wmma::store_matrix_sync(sS + (mt * 16) * LDA + (n0t + 1) * 16, sacc[1], LDA, wmma::mem_row_major);
        }
        __syncthreads();

        float sv[4][4];
        #pragma unroll
        for (int i = 0; i < 4; i++) {
            float4 v4 = *(const float4*)(sS + (ty + 16 * i) * LDA + tx * 4);
            sv[i][0] = v4.x * 0.125f; sv[i][1] = v4.y * 0.125f;
            sv[i][2] = v4.z * 0.125f; sv[i][3] = v4.w * 0.125f;
        }
        if (kt == qt) {
            #pragma unroll
            for (int i = 0; i < 4; i++)
                #pragma unroll
                for (int j = 0; j < 4; j++)
                    if (tx * 4 + j > ty + 16 * i) sv[i][j] = IGNORE_VAL;
        }

        float mx[4];
        #pragma unroll
        for (int i = 0; i < 4; i++)
            mx[i] = fmaxf(fmaxf(sv[i][0], sv[i][1]), fmaxf(sv[i][2], sv[i][3]));
        #pragma unroll
        for (int o = 8; o > 0; o >>= 1)
            #pragma unroll
            for (int i = 0; i < 4; i++)
                mx[i] = fmaxf(mx[i], __shfl_xor_sync(0xffffffffu, mx[i], o));

        float alpha[4];
        #pragma unroll
        for (int i = 0; i < 4; i++) {
            float mnew = fmaxf(m_i[i], mx[i]);
            alpha[i] = __expf(m_i[i] - mnew);
            m_i[i] = mnew;
        }
        #pragma unroll
        for (int i = 0; i < 4; i++)
            #pragma unroll
            for (int j = 0; j < 4; j++)
                sv[i][j] = __expf(sv[i][j] - m_i[i]);

        float rs[4];
        #pragma unroll
        for (int i = 0; i < 4; i++)
            rs[i] = (sv[i][0] + sv[i][1]) + (sv[i][2] + sv[i][3]);
        #pragma unroll
        for (int o = 8; o > 0; o >>= 1)
            #pragma unroll
            for (int i = 0; i < 4; i++)
                rs[i] += __shfl_xor_sync(0xffffffffu, rs[i], o);
        #pragma unroll
        for (int i = 0; i < 4; i++)
            l_i[i] = l_i[i] * alpha[i] + rs[i];

        #pragma unroll
        for (int i = 0; i < 4; i++) {
            int off = (ty + 16 * i) * LDA + tx * 4;
            #pragma unroll
            for (int j = 0; j < 4; j++) {
                __nv_bfloat16 hi = __float2bfloat16(sv[i][j]);
                __nv_bfloat16 lo = __float2bfloat16(sv[i][j] - __bfloat162float(hi));
                sKh[off + j] = hi;
                sKl[off + j] = lo;
            }
        }
        __syncthreads();

        {
            wmma::fragment<wmma::accumulator, 16, 16, 16, float> pacc[2];
            wmma::fill_fragment(pacc[0], 0.0f);
            wmma::fill_fragment(pacc[1], 0.0f);
            #pragma unroll
            for (int ks = 0; ks < 4; ks++) {
                wmma::fragment<wmma::matrix_a, 16, 16, 16, __nv_bfloat16, wmma::row_major> pH, pL;
                wmma::load_matrix_sync(pH, sKh + (mt * 16) * LDA + ks * 16, LDA);
                wmma::load_matrix_sync(pL, sKl + (mt * 16) * LDA + ks * 16, LDA);
                #pragma unroll
                for (int j = 0; j < 2; j++) {
                    wmma::fragment<wmma::matrix_b, 16, 16, 16, __nv_bfloat16, wmma::row_major> vH, vL;
                    wmma::load_matrix_sync(vH, sVh + (ks * 16) * LDA + (n0t + j) * 16, LDA);
                    wmma::load_matrix_sync(vL, sVl + (ks * 16) * LDA + (n0t + j) * 16, LDA);
                    wmma::mma_sync(pacc[j], pH, vH, pacc[j]);
                    wmma::mma_sync(pacc[j], pH, vL, pacc[j]);
                    wmma::mma_sync(pacc[j], pL, vH, pacc[j]);
                }
            }
            wmma::store_matrix_sync(sS + (mt * 16) * LDA + n0t * 16, pacc[0], LDA, wmma::mem_row_major);
            wmma::store_matrix_sync(sS + (mt * 16) * LDA + (n0t + 1) * 16, pacc[1], LDA, wmma::mem_row_major);
        }
        __syncthreads();

        #pragma unroll
        for (int i = 0; i < 4; i++) {
            float4 v4 = *(const float4*)(sS + (ty + 16 * i) * LDA + tx * 4);
            acc[i][0] = acc[i][0] * alpha[i] + v4.x;
            acc[i][1] = acc[i][1] * alpha[i] + v4.y;
            acc[i][2] = acc[i][2] * alpha[i] + v4.z;
            acc[i][3] = acc[i][3] * alpha[i] + v4.w;
        }
        __syncthreads();
    }

    const int b = bh >> 4, h = bh & 15;
    #pragma unroll
    for (int i = 0; i < 4; i++) {
        float inv = 1.f / l_i[i];
        int q = qt * 64 + ty + 16 * i;
        size_t base = (size_t)(b * S + q) * DM + h * DH + tx * 4;
        #pragma unroll
        for (int j = 0; j < 4; j++) {
            float v = acc[i][j] * inv;
            __nv_bfloat16 hi = __float2bfloat16(v);
            __nv_bfloat16 lo = __float2bfloat16(v - __bfloat162float(hi));
            g_zh[base + j] = hi;
            g_zl[base + j] = lo;
        }
    }
}

// ---------------------------------------------------------------------------
extern "C" void kernel_launch(void* const* d_in, const int* in_sizes, int n_in,
                              void* d_out, int out_size) {
    const float* x   = (const float*)d_in[0];
    const float* W_Q = (const float*)d_in[1];
    const float* W_K = (const float*)d_in[2];
    const float* W_V = (const float*)d_in[3];
    const float* W_O = (const float*)d_in[4];
    const float* b_Q = (const float*)d_in[5];
    const float* b_K = (const float*)d_in[6];
    const float* b_V = (const float*)d_in[7];
    const float* b_O = (const float*)d_in[8];
    float* out = (float*)d_out;

    cudaFuncSetAttribute(attn_wmma, cudaFuncAttributeMaxDynamicSharedMemorySize, ATT_SMEM);
    cudaFuncSetAttribute(gemm_wmma<0>, cudaFuncAttributeMaxDynamicSharedMemorySize, GSMEM_B);
    cudaFuncSetAttribute(gemm_wmma<1>, cudaFuncAttributeMaxDynamicSharedMemorySize, GSMEM_B);

    // Pre-passes
    split_x_kernel<<<(MTOT * DM + 255) / 256, 256>>>(x);
    pack_wqkv_kernel<<<(NQKV * DM + 255) / 256, 256>>>(W_Q, W_K, W_V);
    pack_wo_kernel<<<(DM * DM + 255) / 256, 256>>>(W_O);

    // QKV projection
    {
        dim3 g(MTOT / 128, NQKV / 128);
        gemm_wmma<0><<<g, 512, GSMEM_B>>>(b_Q, b_K, b_V, b_O, out);
    }

    // Flash attention (wmma)
    {
        dim3 g(S / 64, BH);
        attn_wmma<<<g, 256, ATT_SMEM>>>();
    }

    // O projection
    {
        dim3 g(MTOT / 128, DM / 128);
        gemm_wmma<1><<<g, 512, GSMEM_B>>>(b_Q, b_K, b_V, b_O, out);
    }
}